// round 11
// baseline (speedup 1.0000x reference)
#include <cuda_runtime.h>

#define TLEN 4096
#define BROWS 2048
#define SHIFTW 10
#define NSHIFT 21
#define THREADS 256

// class-interleaved quad layouts: slot(Qp) = (Qp&3)*H + (Qp>>2), float4 slots
#define HQY 258                 /* y: 1024 quads + 8 halo, offset QOFF=4 */
#define HQX 256                 /* x: 1024 quads, no halo */

__device__ float g_row_mse[BROWS];
__device__ unsigned int g_done = 0;

__global__ __launch_bounds__(THREADS, 4) void shift_loss_kernel(
    const float* __restrict__ x, const float* __restrict__ y,
    float* __restrict__ out)
{
    const int row = blockIdx.x;
    const float* __restrict__ xr = x + (size_t)row * TLEN;
    const float* __restrict__ yr = y + (size_t)row * TLEN;
    const int tid = threadIdx.x;
    const int lane = tid & 31;
    const int wid = tid >> 5;

    __shared__ float ysm[4 * HQY * 4];   // y, class-interleaved, zero halo
    __shared__ float xsm[4 * HQX * 4];   // x, class-interleaved
    __shared__ float red[THREADS / 32][25];
    __shared__ float tot[25];
    __shared__ float corr_sh[NSHIFT];
    __shared__ float mse_sh[NSHIFT];
    __shared__ int is_last_sh;

    // ---- zero the 8 y halo quads (Qp = 0..3 and 1028..1031) ----
    if (tid < 8) {
        const int Qp = (tid < 4) ? tid : (1024 + tid);
        float4 z = make_float4(0.f, 0.f, 0.f, 0.f);
        *reinterpret_cast<float4*>(&ysm[(((Qp & 3) * HQY + (Qp >> 2)) << 2)]) = z;
    }

    // ---- stage x and y (coalesced LDG.128 -> interleaved STS.128),
    //      folding row sums into the staging pass ----
    float sx = 0.f, sxx = 0.f, sy = 0.f, syy = 0.f;
#pragma unroll
    for (int it = 0; it < 4; ++it) {
        const int Q = it * THREADS + tid;             // quad index 0..1023
        const float4 vx4 = *reinterpret_cast<const float4*>(xr + Q * 4);
        sx  += vx4.x + vx4.y + vx4.z + vx4.w;
        sxx += vx4.x * vx4.x + vx4.y * vx4.y + vx4.z * vx4.z + vx4.w * vx4.w;
        *reinterpret_cast<float4*>(&xsm[(((Q & 3) * HQX + (Q >> 2)) << 2)]) = vx4;

        const float4 vy4 = *reinterpret_cast<const float4*>(yr + Q * 4);
        sy  += vy4.x + vy4.y + vy4.z + vy4.w;
        syy += vy4.x * vy4.x + vy4.y * vy4.y + vy4.z * vy4.z + vy4.w * vy4.w;
        const int Qp = Q + 4;
        *reinterpret_cast<float4*>(&ysm[(((Qp & 3) * HQY + (Qp >> 2)) << 2)]) = vy4;
    }
    __syncthreads();

    // ---- main pass: thread owns elements [16*tid, 16*tid+16) ----
    float X[16];
#pragma unroll
    for (int k = 0; k < 4; ++k) {                     // x quad 4*tid+k: class k, idx tid
        const float4 v = *reinterpret_cast<const float4*>(&xsm[((k * HQX + tid) << 2)]);
        X[4 * k + 0] = v.x; X[4 * k + 1] = v.y;
        X[4 * k + 2] = v.z; X[4 * k + 3] = v.w;
    }

    float acc[NSHIFT];
#pragma unroll
    for (int s = 0; s < NSHIFT; ++s) acc[s] = 0.f;

    // window quads j=0..9 cover y[t0-12 .. t0+27]; Qp = 4*tid+1+j ->
    // class (1+j)&3 (compile-time), idx tid + ((1+j)>>2) (lane-contiguous).
#pragma unroll
    for (int j = 0; j < 10; ++j) {
        const int cls = (1 + j) & 3;
        const int add = (1 + j) >> 2;
        const float4 v = *reinterpret_cast<const float4*>(
            &ysm[((cls * HQY + tid + add) << 2)]);
        const float w4[4] = {v.x, v.y, v.z, v.w};
#pragma unroll
        for (int c = 0; c < 4; ++c) {
            const int d = 4 * (j - 3) + c;            // y offset rel. t0, in [-12,27]
#pragma unroll
            for (int e = 0; e < 16; ++e) {
                const int s = d - e + SHIFTW;         // compile-time after unroll
                if (s >= 0 && s < NSHIFT)
                    acc[s] += X[e] * w4[c];
            }
        }
    }

    // ---- block reduction of 25 partials ----
    float vals[25];
    vals[0] = sx; vals[1] = sxx; vals[2] = sy; vals[3] = syy;
#pragma unroll
    for (int s = 0; s < NSHIFT; ++s) vals[4 + s] = acc[s];

#pragma unroll
    for (int i = 0; i < 25; ++i) {
#pragma unroll
        for (int o = 16; o > 0; o >>= 1)
            vals[i] += __shfl_down_sync(0xffffffffu, vals[i], o);
    }
    if (lane == 0) {
#pragma unroll
        for (int i = 0; i < 25; ++i) red[wid][i] = vals[i];
    }
    __syncthreads();
    if (tid < 25) {
        float t = 0.f;
#pragma unroll
        for (int wb = 0; wb < THREADS / 32; ++wb) t += red[wb][tid];
        tot[tid] = t;
    }
    __syncthreads();

    // ---- 21 threads: per-shift trimmed Pearson + MSE (edges from smem) ----
    if (tid < NSHIFT) {
        const int sh = tid - SHIFTW;
        float Sx = tot[0], Sxx = tot[1], Sy = tot[2], Syy = tot[3];
        const int m = sh < 0 ? -sh : sh;
        const float n = (float)(TLEN - m);
        for (int i = 0; i < m; ++i) {
            // sh>0 trims x tail & y head; sh<0 trims x head & y tail
            const int gx = (sh > 0) ? (TLEN - 1 - i) : i;
            const int gy = (sh > 0) ? i : (TLEN - 1 - i);
            const int Qx = gx >> 2;
            const float xv2 = xsm[(((Qx & 3) * HQX + (Qx >> 2)) << 2) + (gx & 3)];
            const int Qy = (gy >> 2) + 4;
            const float yv2 = ysm[(((Qy & 3) * HQY + (Qy >> 2)) << 2) + (gy & 3)];
            Sx -= xv2; Sxx -= xv2 * xv2;
            Sy -= yv2; Syy -= yv2 * yv2;
        }
        const float Sxy = tot[4 + tid];
        const float inv_n = 1.f / n;
        const float cov = Sxy - Sx * Sy * inv_n;
        const float vx  = Sxx - Sx * Sx * inv_n;
        const float vy  = Syy - Sy * Sy * inv_n;
        corr_sh[tid] = cov * rsqrtf(vx * vy);
        mse_sh[tid]  = (Sxx + Syy - 2.f * Sxy) * inv_n;
    }
    __syncthreads();

    if (tid == 0) {
        float best = corr_sh[0];
        int bi = 0;
#pragma unroll
        for (int s = 1; s < NSHIFT; ++s) {
            if (corr_sh[s] > best) { best = corr_sh[s]; bi = s; }  // first-max tie-break
        }
        g_row_mse[row] = mse_sh[bi];
        __threadfence();
        const unsigned int prev = atomicAdd(&g_done, 1u);
        is_last_sh = (prev == BROWS - 1u) ? 1 : 0;
    }
    __syncthreads();

    // ---- last block: fused final mean (deterministic fixed-order sum) ----
    if (is_last_sh) {
        float s = 0.f;
#pragma unroll
        for (int i = 0; i < BROWS / THREADS; ++i)
            s += __ldcg(&g_row_mse[i * THREADS + tid]);
#pragma unroll
        for (int o = 16; o > 0; o >>= 1) s += __shfl_down_sync(0xffffffffu, s, o);
        if (lane == 0) red[wid][0] = s;
        __syncthreads();
        if (tid == 0) {
            float t = 0.f;
#pragma unroll
            for (int wb = 0; wb < THREADS / 32; ++wb) t += red[wb][0];
            out[0] = t / (float)BROWS;
            g_done = 0;  // reset for next graph replay
        }
    }
}

extern "C" void kernel_launch(void* const* d_in, const int* in_sizes, int n_in,
                              void* d_out, int out_size)
{
    const float* x = (const float*)d_in[0];
    const float* y = (const float*)d_in[1];
    shift_loss_kernel<<<BROWS, THREADS>>>(x, y, (float*)d_out);
}

// round 12
// speedup vs baseline: 1.1735x; 1.1735x over previous
#include <cuda_runtime.h>

#define TLEN 4096
#define BROWS 2048
#define SHIFTW 10
#define NSHIFT 21
#define THREADS 256
#define HQ 516                  /* y quad slots per class (2 classes) */

__device__ float g_row_mse[BROWS];
__device__ unsigned int g_done = 0;

// y quad Q (elements 4Q..4Q+3) lives at Qp=Q+4; float4 slot = (Qp&1)*HQ + (Qp>>1)
__device__ __forceinline__ int yslot(int Qp) { return (Qp & 1) * HQ + (Qp >> 1); }

__global__ __launch_bounds__(THREADS, 5) void shift_loss_kernel(
    const float* __restrict__ x, const float* __restrict__ y,
    float* __restrict__ out)
{
    const int row = blockIdx.x;
    const float* __restrict__ xr = x + (size_t)row * TLEN;
    const float* __restrict__ yr = y + (size_t)row * TLEN;
    const int tid = threadIdx.x;
    const int lane = tid & 31;
    const int wid = tid >> 5;

    __shared__ float ysm[2 * HQ * 4];    // y, 2-class interleaved, zero halo
    __shared__ float red[THREADS / 32][25];
    __shared__ float tot[25];
    __shared__ float corr_sh[NSHIFT];
    __shared__ float mse_sh[NSHIFT];
    __shared__ float xe_lo[16], xe_hi[16];   // x row edges for trim
    __shared__ int is_last_sh;

    // ---- zero halo quads Qp in {0..3, 1028..1031} ----
    if (tid < 8) {
        const int Qp = (tid < 4) ? tid : (1024 + tid);
        *reinterpret_cast<float4*>(&ysm[yslot(Qp) << 2]) =
            make_float4(0.f, 0.f, 0.f, 0.f);
    }

    // ---- stage y (coalesced LDG.128 -> 2-class STS.128); fold sy/syy ----
    float sy = 0.f, syy = 0.f;
#pragma unroll
    for (int it = 0; it < 4; ++it) {
        const int Q = it * THREADS + tid;            // quad 0..1023
        const float4 v = *reinterpret_cast<const float4*>(yr + Q * 4);
        sy  += v.x + v.y + v.z + v.w;
        syy += v.x * v.x + v.y * v.y + v.z * v.z + v.w * v.w;
        *reinterpret_cast<float4*>(&ysm[yslot(Q + 4) << 2]) = v;
    }
    __syncthreads();

    float acc[NSHIFT];
#pragma unroll
    for (int s = 0; s < NSHIFT; ++s) acc[s] = 0.f;
    float sx = 0.f, sxx = 0.f;

    // ---- main pass: 2 chunks, thread owns elements [8T, 8T+8), T = it*256+tid ----
#pragma unroll
    for (int it = 0; it < 2; ++it) {
        const int T = it * THREADS + tid;            // 0..511
        const int base = T * 8;

        float X[8];
        {
            const float4 a = *reinterpret_cast<const float4*>(xr + base);
            const float4 b = *reinterpret_cast<const float4*>(xr + base + 4);
            X[0] = a.x; X[1] = a.y; X[2] = a.z; X[3] = a.w;
            X[4] = b.x; X[5] = b.y; X[6] = b.z; X[7] = b.w;
        }
#pragma unroll
        for (int e = 0; e < 8; ++e) { sx += X[e]; sxx += X[e] * X[e]; }

        // capture x edges for trim (x[0..9] ⊂ T∈{0,1}; x[4086..4095] ⊂ T∈{510,511})
        if (T < 2) {
#pragma unroll
            for (int e = 0; e < 8; ++e) xe_lo[T * 8 + e] = X[e];
        }
        if (T >= 510) {
#pragma unroll
            for (int e = 0; e < 8; ++e) xe_hi[(T - 510) * 8 + e] = X[e];
        }

        // window quads j=0..7 cover y[base-12 .. base+19];
        // Qp = 2T + j + 1: class (j+1)&1 compile-time, idx T + ((j+1)>>1) contiguous.
#pragma unroll
        for (int j = 0; j < 8; ++j) {
            const int cls = (j + 1) & 1;
            const int add = (j + 1) >> 1;
            const float4 v = *reinterpret_cast<const float4*>(
                &ysm[(cls * HQ + T + add) << 2]);
            const float w4[4] = {v.x, v.y, v.z, v.w};
#pragma unroll
            for (int c = 0; c < 4; ++c) {
                const int d = 4 * j + c - 12;        // y offset rel. base, in [-12,19]
#pragma unroll
                for (int e = 0; e < 8; ++e) {
                    const int s = d - e + SHIFTW;    // compile-time after unroll
                    if (s >= 0 && s < NSHIFT)
                        acc[s] += X[e] * w4[c];
                }
            }
        }
    }

    // ---- block reduction of 25 partials ----
    float vals[25];
    vals[0] = sx; vals[1] = sxx; vals[2] = sy; vals[3] = syy;
#pragma unroll
    for (int s = 0; s < NSHIFT; ++s) vals[4 + s] = acc[s];

#pragma unroll
    for (int i = 0; i < 25; ++i) {
#pragma unroll
        for (int o = 16; o > 0; o >>= 1)
            vals[i] += __shfl_down_sync(0xffffffffu, vals[i], o);
    }
    if (lane == 0) {
#pragma unroll
        for (int i = 0; i < 25; ++i) red[wid][i] = vals[i];
    }
    __syncthreads();
    if (tid < 25) {
        float t = 0.f;
#pragma unroll
        for (int wb = 0; wb < THREADS / 32; ++wb) t += red[wb][tid];
        tot[tid] = t;
    }
    __syncthreads();

    // ---- 21 threads: per-shift trimmed Pearson + MSE (all-smem trim) ----
    if (tid < NSHIFT) {
        const int sh = tid - SHIFTW;
        float Sx = tot[0], Sxx = tot[1], Sy = tot[2], Syy = tot[3];
        const int m = sh < 0 ? -sh : sh;
        const float n = (float)(TLEN - m);
        for (int i = 0; i < m; ++i) {
            // sh>0 trims x tail & y head; sh<0 trims x head & y tail
            const float xv2 = (sh > 0) ? xe_hi[15 - i] : xe_lo[i];
            const int gy = (sh > 0) ? i : (TLEN - 1 - i);
            const float yv2 = ysm[(yslot((gy >> 2) + 4) << 2) + (gy & 3)];
            Sx -= xv2; Sxx -= xv2 * xv2;
            Sy -= yv2; Syy -= yv2 * yv2;
        }
        const float Sxy = tot[4 + tid];
        const float inv_n = 1.f / n;
        const float cov = Sxy - Sx * Sy * inv_n;
        const float vx  = Sxx - Sx * Sx * inv_n;
        const float vy  = Syy - Sy * Sy * inv_n;
        corr_sh[tid] = cov * rsqrtf(vx * vy);
        mse_sh[tid]  = (Sxx + Syy - 2.f * Sxy) * inv_n;
    }
    __syncthreads();

    if (tid == 0) {
        float best = corr_sh[0];
        int bi = 0;
#pragma unroll
        for (int s = 1; s < NSHIFT; ++s) {
            if (corr_sh[s] > best) { best = corr_sh[s]; bi = s; }  // first-max tie-break
        }
        g_row_mse[row] = mse_sh[bi];
        __threadfence();
        const unsigned int prev = atomicAdd(&g_done, 1u);
        is_last_sh = (prev == BROWS - 1u) ? 1 : 0;
    }
    __syncthreads();

    // ---- last block: fused final mean (deterministic fixed-order sum) ----
    if (is_last_sh) {
        float s = 0.f;
#pragma unroll
        for (int i = 0; i < BROWS / THREADS; ++i)
            s += __ldcg(&g_row_mse[i * THREADS + tid]);
#pragma unroll
        for (int o = 16; o > 0; o >>= 1) s += __shfl_down_sync(0xffffffffu, s, o);
        if (lane == 0) red[wid][0] = s;
        __syncthreads();
        if (tid == 0) {
            float t = 0.f;
#pragma unroll
            for (int wb = 0; wb < THREADS / 32; ++wb) t += red[wb][0];
            out[0] = t / (float)BROWS;
            g_done = 0;  // reset for next graph replay
        }
    }
}

extern "C" void kernel_launch(void* const* d_in, const int* in_sizes, int n_in,
                              void* d_out, int out_size)
{
    const float* x = (const float*)d_in[0];
    const float* y = (const float*)d_in[1];
    shift_loss_kernel<<<BROWS, THREADS>>>(x, y, (float*)d_out);
}